// round 14
// baseline (speedup 1.0000x reference)
#include <cuda_runtime.h>
#include <cstdint>

#define B_  4
#define S_  2048
#define D_  768
#define H_  12
#define DK_ 64

__device__ __forceinline__ uint32_t smem_u32(const void* p) {
    uint32_t a; asm("{ .reg .u64 t; cvta.to.shared.u64 t, %1; cvt.u32.u64 %0, t; }" : "=r"(a) : "l"(p));
    return a;
}
__device__ __forceinline__ void cp_async16(uint32_t dst, const void* src) {
    asm volatile("cp.async.cg.shared.global [%0], [%1], 16;" :: "r"(dst), "l"(src) : "memory");
}
#define CP_COMMIT() asm volatile("cp.async.commit_group;" ::: "memory")
#define CP_WAIT(n)  asm volatile("cp.async.wait_group %0;" :: "n"(n) : "memory")

// m16n8k8 tf32 mma (attention)
__device__ __forceinline__ void mma_tf32(float* c, const uint32_t* a, uint32_t b0, uint32_t b1) {
    asm volatile(
        "mma.sync.aligned.m16n8k8.row.col.f32.tf32.tf32.f32 "
        "{%0,%1,%2,%3}, {%4,%5,%6,%7}, {%8,%9}, {%0,%1,%2,%3};"
        : "+f"(c[0]), "+f"(c[1]), "+f"(c[2]), "+f"(c[3])
        : "r"(a[0]), "r"(a[1]), "r"(a[2]), "r"(a[3]), "r"(b0), "r"(b1));
}
// m16n8k16 bf16 mma (projections)
__device__ __forceinline__ void mma_bf16(float* c, const uint32_t* a, uint32_t b0, uint32_t b1) {
    asm volatile(
        "mma.sync.aligned.m16n8k16.row.col.f32.bf16.bf16.f32 "
        "{%0,%1,%2,%3}, {%4,%5,%6,%7}, {%8,%9}, {%0,%1,%2,%3};"
        : "+f"(c[0]), "+f"(c[1]), "+f"(c[2]), "+f"(c[3])
        : "r"(a[0]), "r"(a[1]), "r"(a[2]), "r"(a[3]), "r"(b0), "r"(b1));
}
// bf16x3 pack: hi = bf16x2(x0,x1) (low k in low half), lo = bf16x2 of exact residuals
__device__ __forceinline__ void bf16x3_pack(float x0, float x1, uint32_t& hi, uint32_t& lo) {
    asm("cvt.rn.bf16x2.f32 %0, %1, %2;" : "=r"(hi) : "f"(x1), "f"(x0));
    float h0 = __uint_as_float(hi << 16);
    float h1 = __uint_as_float(hi & 0xFFFF0000u);
    float r0 = x0 - h0;
    float r1 = x1 - h1;
    asm("cvt.rn.bf16x2.f32 %0, %1, %2;" : "=r"(lo) : "f"(r1), "f"(r0));
}
// round-to-nearest tf32
__device__ __forceinline__ uint32_t to_tf32(float x) {
    uint32_t r; asm("cvt.rna.tf32.f32 %0,%1;" : "=r"(r) : "f"(x)); return r;
}
__device__ __forceinline__ float4 round_tf32_4(float4 v) {
    v.x = __uint_as_float(to_tf32(v.x));
    v.y = __uint_as_float(to_tf32(v.y));
    v.z = __uint_as_float(to_tf32(v.z));
    v.w = __uint_as_float(to_tf32(v.w));
    return v;
}

// Scratch
__device__ float g_q[(size_t)B_ * H_ * S_ * DK_];
__device__ float g_k[(size_t)B_ * H_ * S_ * DK_];
__device__ float g_v[(size_t)B_ * H_ * S_ * DK_];
__device__ float g_x[(size_t)B_ * S_ * D_];

// ---------------------------------------------------------------------------
// bf16x3 GEMM with shared hi/lo planes: packing hoisted out of the MMA loop.
// Raw f32 staging (double-buffered, cp.async) -> shared conversion pass ->
// bf16x2 hi/lo planes (single-buffered) -> pure LDS+MMA inner loop.
// ---------------------------------------------------------------------------
#define GK_PITCH 36
#define GK_MATF  (128 * GK_PITCH)            // 4608 floats per raw matrix
#define GK_STAGEF (2 * GK_MATF)              // 9216 floats per raw stage
#define GK_RAWF  (2 * GK_STAGEF)             // 18432 floats (double buffer)
#define PP       18                          // plane pitch (words per row)
#define PLANEW   (128 * PP)                  // 2304 words per plane
#define GK_SMEM  ((GK_RAWF + 4 * PLANEW) * 4)   // 110592 bytes

__device__ __forceinline__ void gemm_body(
    const float* __restrict__ X, const float* __restrict__ W,
    const float* __restrict__ bias, float* __restrict__ out, int scatter)
{
    extern __shared__ float smf[];
    const uint32_t sbase = smem_u32(smf);
    uint32_t* Ahi = (uint32_t*)(smf + GK_RAWF);
    uint32_t* Alo = Ahi + PLANEW;
    uint32_t* Bhi = Alo + PLANEW;
    uint32_t* Blo = Bhi + PLANEW;

    const int tid = threadIdx.x;
    const int lane = tid & 31;
    const int wid = tid >> 5;
    const int wm = (wid & 3) * 32;
    const int wn = (wid >> 2) * 64;
    const int m0 = blockIdx.y * 128;
    const int n0 = blockIdx.x * 128;
    const int g = lane >> 2, t = lane & 3;
    const int crow = tid >> 1;               // conversion row (0..127)
    const int cpb  = (tid & 1) * 8;          // conversion pair base (0 or 8)

    float c[2][8][4];
    #pragma unroll
    for (int mi = 0; mi < 2; mi++)
        #pragma unroll
        for (int nj = 0; nj < 8; nj++)
            #pragma unroll
            for (int q = 0; q < 4; q++) c[mi][nj][q] = 0.0f;

    auto issue = [&](int ch) {
        const int k0 = ch * 32;
        const uint32_t dstA = sbase + (ch & 1) * (GK_STAGEF * 4);
        const uint32_t dstB = dstA + GK_MATF * 4;
        #pragma unroll
        for (int i = 0; i < 4; i++) {
            int idx = tid + 256 * i;
            int r = idx >> 3, c4 = idx & 7;
            cp_async16(dstA + r * (GK_PITCH * 4) + c4 * 16,
                       X + (size_t)(m0 + r) * D_ + k0 + c4 * 4);
            cp_async16(dstB + r * (GK_PITCH * 4) + c4 * 16,
                       W + (size_t)(n0 + r) * D_ + k0 + c4 * 4);
        }
        CP_COMMIT();
    };

    issue(0);
    for (int ch = 0; ch < 24; ch++) {
        if (ch + 1 < 24) { issue(ch + 1); CP_WAIT(1); }
        else             { CP_WAIT(0); }
        __syncthreads();     // raw chunk ch landed; all warps done with planes

        // ---- shared conversion: raw f32 -> bf16 hi/lo planes ----
        {
            const float* rA = smf + (ch & 1) * GK_STAGEF;
            const float* rB = rA + GK_MATF;
            #pragma unroll
            for (int p = 0; p < 8; p++) {
                const int w = crow * PP + cpb + p;
                float2 va = *(const float2*)(rA + crow * GK_PITCH + (cpb + p) * 2);
                float2 vb = *(const float2*)(rB + crow * GK_PITCH + (cpb + p) * 2);
                uint32_t h, l;
                bf16x3_pack(va.x, va.y, h, l);
                Ahi[w] = h; Alo[w] = l;
                bf16x3_pack(vb.x, vb.y, h, l);
                Bhi[w] = h; Blo[w] = l;
            }
        }
        __syncthreads();     // planes ready for all warps

        // ---- pure LDS + MMA inner loop ----
        #pragma unroll
        for (int k16 = 0; k16 < 2; k16++) {
            const int kb8 = k16 * 8;
            uint32_t ah[2][4], al[2][4];
            #pragma unroll
            for (int mi = 0; mi < 2; mi++) {
                const int r0 = wm + mi * 16 + g;
                ah[mi][0] = Ahi[(r0    ) * PP + kb8 + t    ];
                ah[mi][1] = Ahi[(r0 + 8) * PP + kb8 + t    ];
                ah[mi][2] = Ahi[(r0    ) * PP + kb8 + t + 4];
                ah[mi][3] = Ahi[(r0 + 8) * PP + kb8 + t + 4];
                al[mi][0] = Alo[(r0    ) * PP + kb8 + t    ];
                al[mi][1] = Alo[(r0 + 8) * PP + kb8 + t    ];
                al[mi][2] = Alo[(r0    ) * PP + kb8 + t + 4];
                al[mi][3] = Alo[(r0 + 8) * PP + kb8 + t + 4];
            }
            #pragma unroll
            for (int nj = 0; nj < 8; nj++) {
                const int cn = wn + nj * 8 + g;
                uint32_t bh0 = Bhi[cn * PP + kb8 + t    ];
                uint32_t bh1 = Bhi[cn * PP + kb8 + t + 4];
                uint32_t bl0 = Blo[cn * PP + kb8 + t    ];
                uint32_t bl1 = Blo[cn * PP + kb8 + t + 4];
                mma_bf16(c[0][nj], ah[0], bh0, bh1);
                mma_bf16(c[0][nj], ah[0], bl0, bl1);
                mma_bf16(c[0][nj], al[0], bh0, bh1);
                mma_bf16(c[1][nj], ah[1], bh0, bh1);
                mma_bf16(c[1][nj], ah[1], bl0, bl1);
                mma_bf16(c[1][nj], al[1], bh0, bh1);
            }
        }
    }

    #pragma unroll
    for (int nj = 0; nj < 8; nj++) {
        const int n = n0 + wn + nj * 8 + 2 * t;
        const float2 bb = *(const float2*)(bias + n);
        #pragma unroll
        for (int mi = 0; mi < 2; mi++) {
            #pragma unroll
            for (int half = 0; half < 2; half++) {
                const int m = m0 + wm + mi * 16 + g + 8 * half;
                float2 v;
                v.x = c[mi][nj][2 * half + 0] + bb.x;
                v.y = c[mi][nj][2 * half + 1] + bb.y;
                if (scatter) {
                    const int h = n >> 6, dk = n & 63;
                    const int bi = m >> 11, s = m & 2047;
                    *(float2*)(out + ((((size_t)bi * H_ + h) * S_) + s) * DK_ + dk) = v;
                } else {
                    *(float2*)(out + (size_t)m * D_ + n) = v;
                }
            }
        }
    }
}

__global__ __launch_bounds__(256, 2) void gemm_qkv(
    const float* __restrict__ q, const float* __restrict__ k, const float* __restrict__ v,
    const float* __restrict__ Wq, const float* __restrict__ bq,
    const float* __restrict__ Wk, const float* __restrict__ bk,
    const float* __restrict__ Wv, const float* __restrict__ bv,
    float* __restrict__ gq, float* __restrict__ gk, float* __restrict__ gv)
{
    const int z = blockIdx.z;
    const float* X  = (z == 0) ? q  : (z == 1) ? k  : v;
    const float* W  = (z == 0) ? Wq : (z == 1) ? Wk : Wv;
    const float* bb = (z == 0) ? bq : (z == 1) ? bk : bv;
    float* out      = (z == 0) ? gq : (z == 1) ? gk : gv;
    gemm_body(X, W, bb, out, 1);
}

__global__ __launch_bounds__(256, 2) void gemm_out(
    const float* __restrict__ X, const float* __restrict__ W,
    const float* __restrict__ bias, float* __restrict__ out)
{
    gemm_body(X, W, bias, out, 0);
}

// ---------------------------------------------------------------------------
// Tensor-core flash attention v4 (unchanged from R13 — passed at 4.2e-4)
// ---------------------------------------------------------------------------
#define AQ_OFF  0
#define AK_OFF  8704
#define AV_OFF  (AK_OFF + 2 * 4352)
#define AM_OFF  (AV_OFF + 2 * 4608)
#define ATTN_SMEM_BYTES ((AM_OFF + 128) * 4)

__global__ __launch_bounds__(256, 2) void attn_mma(
    const float* __restrict__ gq, const float* __restrict__ gk,
    const float* __restrict__ gv, const int* __restrict__ mask,
    float* __restrict__ gx)
{
    extern __shared__ float sm[];
    const uint32_t sbase = smem_u32(sm);
    float* sQ = sm + AQ_OFF;

    const int tid = threadIdx.x;
    const int wid = tid >> 5;
    const int lane = tid & 31;
    const int g = lane >> 2, t = lane & 3;
    const int q0 = blockIdx.x * 128;
    const int h  = blockIdx.y;
    const int b  = blockIdx.z;
    const int rowA = 16 * wid + g;

    const size_t hb = (((size_t)b * H_ + h) * S_) * DK_;
    const float* Qh = gq + hb;
    const float* Kh = gk + hb;
    const float* Vh = gv + hb;
    const int* mrow = mask + (size_t)b * S_;

    auto issue_kv = [&](int kt, int buf) {
        const uint32_t dK = sbase + (AK_OFF + buf * 4352) * 4;
        const uint32_t dV = sbase + (AV_OFF + buf * 4608) * 4;
        #pragma unroll
        for (int i = 0; i < 4; i++) {
            int idx = tid + 256 * i, r = idx >> 4, c4 = idx & 15;
            cp_async16(dK + r * (68 * 4) + c4 * 16,
                       Kh + (size_t)(kt * 64 + r) * DK_ + c4 * 4);
            cp_async16(dV + r * (72 * 4) + c4 * 16,
                       Vh + (size_t)(kt * 64 + r) * DK_ + c4 * 4);
        }
        if (tid < 16)
            cp_async16(sbase + (AM_OFF + buf * 64) * 4 + tid * 16, mrow + kt * 64 + tid * 4);
        CP_COMMIT();
    };

    auto round_kv = [&](int buf) {
        float* bK = sm + AK_OFF + buf * 4352;
        float* bV = sm + AV_OFF + buf * 4608;
        #pragma unroll
        for (int i = 0; i < 4; i++) {
            int idx = tid + 256 * i, r = idx >> 4, c4 = idx & 15;
            float4* pk = (float4*)(bK + r * 68 + c4 * 4);
            float4* pv = (float4*)(bV + r * 72 + c4 * 4);
            *pk = round_tf32_4(*pk);
            *pv = round_tf32_4(*pv);
        }
    };

    issue_kv(0, 0);
    #pragma unroll
    for (int i = 0; i < 8; i++) {
        int idx = tid + 256 * i, r = idx >> 4, c4 = idx & 15;
        float4 qv = *(const float4*)(Qh + (size_t)(q0 + r) * DK_ + c4 * 4);
        *(float4*)(sQ + r * 68 + c4 * 4) = round_tf32_4(qv);
    }
    CP_WAIT(0);
    __syncthreads();
    round_kv(0);
    __syncthreads();

    float m0r = -1e30f, m1r = -1e30f, l0 = 0.0f, l1 = 0.0f;
    float co[8][4];
    #pragma unroll
    for (int nj = 0; nj < 8; nj++)
        #pragma unroll
        for (int q = 0; q < 4; q++) co[nj][q] = 0.0f;

    const unsigned FULL = 0xffffffffu;
    const int s0l = 4 * g + (t >> 1);
    const int s1l = s0l + 2;
    const int todd = t & 1;

    for (int kt = 0; kt < S_ / 64; kt++) {
        const int cur = kt & 1;
        const float* sK = sm + AK_OFF + cur * 4352;
        const float* sV = sm + AV_OFF + cur * 4608;
        const int*  sMk = (const int*)(sm + AM_OFF + cur * 64);

        if (kt + 1 < S_ / 64) issue_kv(kt + 1, cur ^ 1);

        float cs[8][4];
        #pragma unroll
        for (int nj = 0; nj < 8; nj++)
            #pragma unroll
            for (int q = 0; q < 4; q++) cs[nj][q] = 0.0f;

        #pragma unroll
        for (int ks = 0; ks < 8; ks++) {
            const int kb = ks * 8;
            uint32_t a[4];
            a[0] = __float_as_uint(sQ[(rowA    ) * 68 + kb + t    ]);
            a[1] = __float_as_uint(sQ[(rowA + 8) * 68 + kb + t    ]);
            a[2] = __float_as_uint(sQ[(rowA    ) * 68 + kb + t + 4]);
            a[3] = __float_as_uint(sQ[(rowA + 8) * 68 + kb + t + 4]);
            #pragma unroll
            for (int nj = 0; nj < 8; nj++) {
                uint32_t b0 = __float_as_uint(sK[(g + 8 * nj) * 68 + kb + t    ]);
                uint32_t b1 = __float_as_uint(sK[(g + 8 * nj) * 68 + kb + t + 4]);
                mma_tf32(cs[nj], a, b0, b1);
            }
        }

        float mx0 = -1e30f, mx1 = -1e30f;
        #pragma unroll
        for (int nj = 0; nj < 8; nj++) {
            const int c0m = sMk[8 * nj + 2 * t];
            const int c1m = sMk[8 * nj + 2 * t + 1];
            cs[nj][0] = c0m ? cs[nj][0] * 0.125f : -1e9f;
            cs[nj][1] = c1m ? cs[nj][1] * 0.125f : -1e9f;
            cs[nj][2] = c0m ? cs[nj][2] * 0.125f : -1e9f;
            cs[nj][3] = c1m ? cs[nj][3] * 0.125f : -1e9f;
            mx0 = fmaxf(mx0, fmaxf(cs[nj][0], cs[nj][1]));
            mx1 = fmaxf(mx1, fmaxf(cs[nj][2], cs[nj][3]));
        }
        #pragma unroll
        for (int d = 1; d < 4; d <<= 1) {
            mx0 = fmaxf(mx0, __shfl_xor_sync(FULL, mx0, d));
            mx1 = fmaxf(mx1, __shfl_xor_sync(FULL, mx1, d));
        }
        const float mn0 = fmaxf(m0r, mx0);
        const float mn1 = fmaxf(m1r, mx1);
        const float cr0 = __expf(m0r - mn0);
        const float cr1 = __expf(m1r - mn1);
        #pragma unroll
        for (int nj = 0; nj < 8; nj++) {
            co[nj][0] *= cr0; co[nj][1] *= cr0;
            co[nj][2] *= cr1; co[nj][3] *= cr1;
        }
        float ps0 = 0.0f, ps1 = 0.0f;
        #pragma unroll
        for (int nj = 0; nj < 8; nj++) {
            cs[nj][0] = __expf(cs[nj][0] - mn0);
            cs[nj][1] = __expf(cs[nj][1] - mn0);
            cs[nj][2] = __expf(cs[nj][2] - mn1);
            cs[nj][3] = __expf(cs[nj][3] - mn1);
            ps0 += cs[nj][0] + cs[nj][1];
            ps1 += cs[nj][2] + cs[nj][3];
        }
        #pragma unroll
        for (int d = 1; d < 4; d <<= 1) {
            ps0 += __shfl_xor_sync(FULL, ps0, d);
            ps1 += __shfl_xor_sync(FULL, ps1, d);
        }
        l0 = l0 * cr0 + ps0;
        l1 = l1 * cr1 + ps1;
        m0r = mn0; m1r = mn1;

        #pragma unroll
        for (int ks = 0; ks < 8; ks++) {
            float x0 = __shfl_sync(FULL, cs[ks][0], s0l);
            float x1 = __shfl_sync(FULL, cs[ks][1], s0l);
            float x2 = __shfl_sync(FULL, cs[ks][2], s0l);
            float x3 = __shfl_sync(FULL, cs[ks][3], s0l);
            float y0 = __shfl_sync(FULL, cs[ks][0], s1l);
            float y1 = __shfl_sync(FULL, cs[ks][1], s1l);
            float y2 = __shfl_sync(FULL, cs[ks][2], s1l);
            float y3 = __shfl_sync(FULL, cs[ks][3], s1l);
            uint32_t a[4];
            a[0] = to_tf32(todd ? x1 : x0);
            a[1] = to_tf32(todd ? x3 : x2);
            a[2] = to_tf32(todd ? y1 : y0);
            a[3] = to_tf32(todd ? y3 : y2);
            const int kb = ks * 8;
            #pragma unroll
            for (int nj = 0; nj < 8; nj++) {
                uint32_t b0 = __float_as_uint(sV[(kb + t    ) * 72 + 8 * nj + g]);
                uint32_t b1 = __float_as_uint(sV[(kb + t + 4) * 72 + 8 * nj + g]);
                mma_tf32(co[nj], a, b0, b1);
            }
        }

        if (kt + 1 < S_ / 64) {
            CP_WAIT(0);
            __syncthreads();
            round_kv(cur ^ 1);
            __syncthreads();
        }
    }

    const float inv0 = 1.0f / l0;
    const float inv1 = 1.0f / l1;
    #pragma unroll
    for (int nj = 0; nj < 8; nj++) {
        const int d = 8 * nj + 2 * t;
        float2 v0 = make_float2(co[nj][0] * inv0, co[nj][1] * inv0);
        float2 v1 = make_float2(co[nj][2] * inv1, co[nj][3] * inv1);
        *(float2*)(gx + ((size_t)b * S_ + q0 + rowA    ) * D_ + h * DK_ + d) = v0;
        *(float2*)(gx + ((size_t)b * S_ + q0 + rowA + 8) * D_ + h * DK_ + d) = v1;
    }
}

extern "C" void kernel_launch(void* const* d_in, const int* in_sizes, int n_in,
                              void* d_out, int out_size)
{
    const float* query = (const float*)d_in[0];
    const float* key_  = (const float*)d_in[1];
    const float* value = (const float*)d_in[2];
    const int*   mask  = (const int*)d_in[3];
    const float* Wq = (const float*)d_in[4];
    const float* bq = (const float*)d_in[5];
    const float* Wk = (const float*)d_in[6];
    const float* bk = (const float*)d_in[7];
    const float* Wv = (const float*)d_in[8];
    const float* bv = (const float*)d_in[9];
    const float* Wo = (const float*)d_in[10];
    const float* bo = (const float*)d_in[11];
    float* out = (float*)d_out;

    float *gq, *gk, *gv, *gx;
    cudaGetSymbolAddress((void**)&gq, g_q);
    cudaGetSymbolAddress((void**)&gk, g_k);
    cudaGetSymbolAddress((void**)&gv, g_v);
    cudaGetSymbolAddress((void**)&gx, g_x);

    cudaFuncSetAttribute(gemm_qkv, cudaFuncAttributeMaxDynamicSharedMemorySize, GK_SMEM);
    cudaFuncSetAttribute(gemm_out, cudaFuncAttributeMaxDynamicSharedMemorySize, GK_SMEM);
    cudaFuncSetAttribute(attn_mma, cudaFuncAttributeMaxDynamicSharedMemorySize, ATTN_SMEM_BYTES);

    dim3 gProj(D_ / 128, (B_ * S_) / 128, 3);   // (6, 64, 3)
    gemm_qkv<<<gProj, 256, GK_SMEM>>>(query, key_, value, Wq, bq, Wk, bk, Wv, bv, gq, gk, gv);

    dim3 gAttn(S_ / 128, H_, B_);               // (16, 12, 4)
    attn_mma<<<gAttn, 256, ATTN_SMEM_BYTES>>>(gq, gk, gv, mask, gx);

    dim3 gOut(D_ / 128, (B_ * S_) / 128);       // (6, 64)
    gemm_out<<<gOut, 256, GK_SMEM>>>(gx, Wo, bo, out);
}

// round 16
// speedup vs baseline: 1.0898x; 1.0898x over previous
#include <cuda_runtime.h>
#include <cstdint>

#define B_  4
#define S_  2048
#define D_  768
#define H_  12
#define DK_ 64

__device__ __forceinline__ uint32_t smem_u32(const void* p) {
    uint32_t a; asm("{ .reg .u64 t; cvta.to.shared.u64 t, %1; cvt.u32.u64 %0, t; }" : "=r"(a) : "l"(p));
    return a;
}
__device__ __forceinline__ void cp_async16(uint32_t dst, const void* src) {
    asm volatile("cp.async.cg.shared.global [%0], [%1], 16;" :: "r"(dst), "l"(src) : "memory");
}
#define CP_COMMIT() asm volatile("cp.async.commit_group;" ::: "memory")
#define CP_WAIT(n)  asm volatile("cp.async.wait_group %0;" :: "n"(n) : "memory")

// m16n8k8 tf32 mma (attention)
__device__ __forceinline__ void mma_tf32(float* c, const uint32_t* a, uint32_t b0, uint32_t b1) {
    asm volatile(
        "mma.sync.aligned.m16n8k8.row.col.f32.tf32.tf32.f32 "
        "{%0,%1,%2,%3}, {%4,%5,%6,%7}, {%8,%9}, {%0,%1,%2,%3};"
        : "+f"(c[0]), "+f"(c[1]), "+f"(c[2]), "+f"(c[3])
        : "r"(a[0]), "r"(a[1]), "r"(a[2]), "r"(a[3]), "r"(b0), "r"(b1));
}
// m16n8k16 bf16 mma (projections)
__device__ __forceinline__ void mma_bf16(float* c, const uint32_t* a, uint32_t b0, uint32_t b1) {
    asm volatile(
        "mma.sync.aligned.m16n8k16.row.col.f32.bf16.bf16.f32 "
        "{%0,%1,%2,%3}, {%4,%5,%6,%7}, {%8,%9}, {%0,%1,%2,%3};"
        : "+f"(c[0]), "+f"(c[1]), "+f"(c[2]), "+f"(c[3])
        : "r"(a[0]), "r"(a[1]), "r"(a[2]), "r"(a[3]), "r"(b0), "r"(b1));
}
// bf16x3 pack: hi = bf16x2(x0,x1) (low k in low half), lo = bf16x2 of exact residuals
__device__ __forceinline__ void bf16x3_pack(float x0, float x1, uint32_t& hi, uint32_t& lo) {
    asm("cvt.rn.bf16x2.f32 %0, %1, %2;" : "=r"(hi) : "f"(x1), "f"(x0));
    float h0 = __uint_as_float(hi << 16);
    float h1 = __uint_as_float(hi & 0xFFFF0000u);
    float r0 = x0 - h0;
    float r1 = x1 - h1;
    asm("cvt.rn.bf16x2.f32 %0, %1, %2;" : "=r"(lo) : "f"(r1), "f"(r0));
}
// round-to-nearest tf32
__device__ __forceinline__ uint32_t to_tf32(float x) {
    uint32_t r; asm("cvt.rna.tf32.f32 %0,%1;" : "=r"(r) : "f"(x)); return r;
}
__device__ __forceinline__ float4 round_tf32_4(float4 v) {
    v.x = __uint_as_float(to_tf32(v.x));
    v.y = __uint_as_float(to_tf32(v.y));
    v.z = __uint_as_float(to_tf32(v.z));
    v.w = __uint_as_float(to_tf32(v.w));
    return v;
}

// Scratch
__device__ float g_q[(size_t)B_ * H_ * S_ * DK_];
__device__ float g_k[(size_t)B_ * H_ * S_ * DK_];
__device__ float g_v[(size_t)B_ * H_ * S_ * DK_];
__device__ float g_x[(size_t)B_ * S_ * D_];
// Pre-split weight planes: 4 matrices x 768 rows x 384 bf16x2 words
#define WPLANE (768 * 384)
__device__ uint32_t g_whi[4 * WPLANE];
__device__ uint32_t g_wlo[4 * WPLANE];

// ---------------------------------------------------------------------------
// Prologue: split all 4 weight matrices into bf16 hi/lo planes (one shot).
// ---------------------------------------------------------------------------
__global__ void split_w_kernel(
    const float* __restrict__ Wq, const float* __restrict__ Wk,
    const float* __restrict__ Wv, const float* __restrict__ Wo)
{
    const int z = blockIdx.z;
    const float* W = (z == 0) ? Wq : (z == 1) ? Wk : (z == 2) ? Wv : Wo;
    const int idx = blockIdx.x * 256 + threadIdx.x;   // word index 0..294911
    float2 v = *(const float2*)(W + (size_t)idx * 2);
    uint32_t h, l;
    bf16x3_pack(v.x, v.y, h, l);
    g_whi[(size_t)z * WPLANE + idx] = h;
    g_wlo[(size_t)z * WPLANE + idx] = l;
}

// ---------------------------------------------------------------------------
// bf16x3 GEMM: A raw f32 (in-register pack); B from pre-split global hi/lo
// planes via cp.async (zero B-side ALU, same smem bytes as the f32 replaced).
// ---------------------------------------------------------------------------
#define GK_PITCH 36
#define GK_MATF  (128 * GK_PITCH)            // 4608 floats per A stage
#define BPP      20                          // B plane pitch (words)
#define BPLANE   (128 * BPP)                 // 2560 words per plane
#define SB_OFF   (2 * GK_MATF)               // B planes start (word offset)
#define GK_SMEM  ((2 * GK_MATF + 4 * BPLANE) * 4)   // 77824 bytes

__device__ __forceinline__ void gemm_body(
    const float* __restrict__ X,
    const uint32_t* __restrict__ whi, const uint32_t* __restrict__ wlo,
    const float* __restrict__ bias, float* __restrict__ out, int scatter)
{
    extern __shared__ float smf[];
    const uint32_t sbase = smem_u32(smf);
    const int tid = threadIdx.x;
    const int lane = tid & 31;
    const int wid = tid >> 5;
    const int wm = (wid & 3) * 32;
    const int wn = (wid >> 2) * 64;
    const int m0 = blockIdx.y * 128;
    const int n0 = blockIdx.x * 128;
    const int g = lane >> 2, t = lane & 3;

    float c[2][8][4];
    #pragma unroll
    for (int mi = 0; mi < 2; mi++)
        #pragma unroll
        for (int nj = 0; nj < 8; nj++)
            #pragma unroll
            for (int q = 0; q < 4; q++) c[mi][nj][q] = 0.0f;

    auto issue = [&](int ch) {
        const int k0 = ch * 32;
        const uint32_t dstA = sbase + (ch & 1) * (GK_MATF * 4);
        const uint32_t dstH = sbase + (SB_OFF + (ch & 1) * 2 * BPLANE) * 4;
        const uint32_t dstL = dstH + BPLANE * 4;
        #pragma unroll
        for (int i = 0; i < 4; i++) {
            int idx = tid + 256 * i;
            int r = idx >> 3, c4 = idx & 7;
            cp_async16(dstA + r * (GK_PITCH * 4) + c4 * 16,
                       X + (size_t)(m0 + r) * D_ + k0 + c4 * 4);
        }
        #pragma unroll
        for (int i = 0; i < 2; i++) {
            int idx = tid + 256 * i;              // 0..511
            int r = idx >> 2, q4 = (idx & 3) * 4; // word group
            const size_t src = (size_t)(n0 + r) * 384 + ch * 16 + q4;
            cp_async16(dstH + (r * BPP + q4) * 4, whi + src);
            cp_async16(dstL + (r * BPP + q4) * 4, wlo + src);
        }
        CP_COMMIT();
    };

    issue(0);
    for (int ch = 0; ch < 24; ch++) {
        if (ch + 1 < 24) { issue(ch + 1); CP_WAIT(1); }
        else             { CP_WAIT(0); }
        __syncthreads();

        const float* rA = smf + (ch & 1) * GK_MATF;
        const uint32_t* BhiS = (const uint32_t*)(smf + SB_OFF + (ch & 1) * 2 * BPLANE);
        const uint32_t* BloS = BhiS + BPLANE;

        #pragma unroll
        for (int k16 = 0; k16 < 2; k16++) {
            const int kb = k16 * 16;     // element base
            const int wb = k16 * 8;      // word (pair) base
            uint32_t ah[2][4], al[2][4];
            #pragma unroll
            for (int mi = 0; mi < 2; mi++) {
                const int r0 = wm + mi * 16 + g;
                float2 p0 = *(const float2*)(rA + (r0    ) * GK_PITCH + kb + 2 * t);
                float2 p1 = *(const float2*)(rA + (r0 + 8) * GK_PITCH + kb + 2 * t);
                float2 p2 = *(const float2*)(rA + (r0    ) * GK_PITCH + kb + 2 * t + 8);
                float2 p3 = *(const float2*)(rA + (r0 + 8) * GK_PITCH + kb + 2 * t + 8);
                bf16x3_pack(p0.x, p0.y, ah[mi][0], al[mi][0]);
                bf16x3_pack(p1.x, p1.y, ah[mi][1], al[mi][1]);
                bf16x3_pack(p2.x, p2.y, ah[mi][2], al[mi][2]);
                bf16x3_pack(p3.x, p3.y, ah[mi][3], al[mi][3]);
            }
            #pragma unroll
            for (int nj = 0; nj < 8; nj++) {
                const int cn = wn + nj * 8 + g;
                uint32_t bh0 = BhiS[cn * BPP + wb + t    ];
                uint32_t bh1 = BhiS[cn * BPP + wb + t + 4];
                uint32_t bl0 = BloS[cn * BPP + wb + t    ];
                uint32_t bl1 = BloS[cn * BPP + wb + t + 4];
                mma_bf16(c[0][nj], ah[0], bh0, bh1);
                mma_bf16(c[0][nj], ah[0], bl0, bl1);
                mma_bf16(c[0][nj], al[0], bh0, bh1);
                mma_bf16(c[1][nj], ah[1], bh0, bh1);
                mma_bf16(c[1][nj], ah[1], bl0, bl1);
                mma_bf16(c[1][nj], al[1], bh0, bh1);
            }
        }
        __syncthreads();
    }

    #pragma unroll
    for (int nj = 0; nj < 8; nj++) {
        const int n = n0 + wn + nj * 8 + 2 * t;
        const float2 bb = *(const float2*)(bias + n);
        #pragma unroll
        for (int mi = 0; mi < 2; mi++) {
            #pragma unroll
            for (int half = 0; half < 2; half++) {
                const int m = m0 + wm + mi * 16 + g + 8 * half;
                float2 v;
                v.x = c[mi][nj][2 * half + 0] + bb.x;
                v.y = c[mi][nj][2 * half + 1] + bb.y;
                if (scatter) {
                    const int h = n >> 6, dk = n & 63;
                    const int bi = m >> 11, s = m & 2047;
                    *(float2*)(out + ((((size_t)bi * H_ + h) * S_) + s) * DK_ + dk) = v;
                } else {
                    *(float2*)(out + (size_t)m * D_ + n) = v;
                }
            }
        }
    }
}

__global__ __launch_bounds__(256, 2) void gemm_qkv(
    const float* __restrict__ q, const float* __restrict__ k, const float* __restrict__ v,
    const float* __restrict__ bq, const float* __restrict__ bk, const float* __restrict__ bv,
    float* __restrict__ gq, float* __restrict__ gk, float* __restrict__ gv)
{
    const int z = blockIdx.z;
    const float* X  = (z == 0) ? q  : (z == 1) ? k  : v;
    const float* bb = (z == 0) ? bq : (z == 1) ? bk : bv;
    float* out      = (z == 0) ? gq : (z == 1) ? gk : gv;
    gemm_body(X, g_whi + (size_t)z * WPLANE, g_wlo + (size_t)z * WPLANE, bb, out, 1);
}

__global__ __launch_bounds__(256, 2) void gemm_out(
    const float* __restrict__ X, const float* __restrict__ bias, float* __restrict__ out)
{
    gemm_body(X, g_whi + (size_t)3 * WPLANE, g_wlo + (size_t)3 * WPLANE, bias, out, 0);
}

// ---------------------------------------------------------------------------
// Tensor-core flash attention v4 (unchanged — passed at 4.2e-4)
// ---------------------------------------------------------------------------
#define AQ_OFF  0
#define AK_OFF  8704
#define AV_OFF  (AK_OFF + 2 * 4352)
#define AM_OFF  (AV_OFF + 2 * 4608)
#define ATTN_SMEM_BYTES ((AM_OFF + 128) * 4)

__global__ __launch_bounds__(256, 2) void attn_mma(
    const float* __restrict__ gq, const float* __restrict__ gk,
    const float* __restrict__ gv, const int* __restrict__ mask,
    float* __restrict__ gx)
{
    extern __shared__ float sm[];
    const uint32_t sbase = smem_u32(sm);
    float* sQ = sm + AQ_OFF;

    const int tid = threadIdx.x;
    const int wid = tid >> 5;
    const int lane = tid & 31;
    const int g = lane >> 2, t = lane & 3;
    const int q0 = blockIdx.x * 128;
    const int h  = blockIdx.y;
    const int b  = blockIdx.z;
    const int rowA = 16 * wid + g;

    const size_t hb = (((size_t)b * H_ + h) * S_) * DK_;
    const float* Qh = gq + hb;
    const float* Kh = gk + hb;
    const float* Vh = gv + hb;
    const int* mrow = mask + (size_t)b * S_;

    auto issue_kv = [&](int kt, int buf) {
        const uint32_t dK = sbase + (AK_OFF + buf * 4352) * 4;
        const uint32_t dV = sbase + (AV_OFF + buf * 4608) * 4;
        #pragma unroll
        for (int i = 0; i < 4; i++) {
            int idx = tid + 256 * i, r = idx >> 4, c4 = idx & 15;
            cp_async16(dK + r * (68 * 4) + c4 * 16,
                       Kh + (size_t)(kt * 64 + r) * DK_ + c4 * 4);
            cp_async16(dV + r * (72 * 4) + c4 * 16,
                       Vh + (size_t)(kt * 64 + r) * DK_ + c4 * 4);
        }
        if (tid < 16)
            cp_async16(sbase + (AM_OFF + buf * 64) * 4 + tid * 16, mrow + kt * 64 + tid * 4);
        CP_COMMIT();
    };

    auto round_kv = [&](int buf) {
        float* bK = sm + AK_OFF + buf * 4352;
        float* bV = sm + AV_OFF + buf * 4608;
        #pragma unroll
        for (int i = 0; i < 4; i++) {
            int idx = tid + 256 * i, r = idx >> 4, c4 = idx & 15;
            float4* pk = (float4*)(bK + r * 68 + c4 * 4);
            float4* pv = (float4*)(bV + r * 72 + c4 * 4);
            *pk = round_tf32_4(*pk);
            *pv = round_tf32_4(*pv);
        }
    };

    issue_kv(0, 0);
    #pragma unroll
    for (int i = 0; i < 8; i++) {
        int idx = tid + 256 * i, r = idx >> 4, c4 = idx & 15;
        float4 qv = *(const float4*)(Qh + (size_t)(q0 + r) * DK_ + c4 * 4);
        *(float4*)(sQ + r * 68 + c4 * 4) = round_tf32_4(qv);
    }
    CP_WAIT(0);
    __syncthreads();
    round_kv(0);
    __syncthreads();

    float m0r = -1e30f, m1r = -1e30f, l0 = 0.0f, l1 = 0.0f;
    float co[8][4];
    #pragma unroll
    for (int nj = 0; nj < 8; nj++)
        #pragma unroll
        for (int q = 0; q < 4; q++) co[nj][q] = 0.0f;

    const unsigned FULL = 0xffffffffu;
    const int s0l = 4 * g + (t >> 1);
    const int s1l = s0l + 2;
    const int todd = t & 1;

    for (int kt = 0; kt < S_ / 64; kt++) {
        const int cur = kt & 1;
        const float* sK = sm + AK_OFF + cur * 4352;
        const float* sV = sm + AV_OFF + cur * 4608;
        const int*  sMk = (const int*)(sm + AM_OFF + cur * 64);

        if (kt + 1 < S_ / 64) issue_kv(kt + 1, cur ^ 1);

        float cs[8][4];
        #pragma unroll
        for (int nj = 0; nj < 8; nj++)
            #pragma unroll
            for (int q = 0; q < 4; q++) cs[nj][q] = 0.0f;

        #pragma unroll
        for (int ks = 0; ks < 8; ks++) {
            const int kb = ks * 8;
            uint32_t a[4];
            a[0] = __float_as_uint(sQ[(rowA    ) * 68 + kb + t    ]);
            a[1] = __float_as_uint(sQ[(rowA + 8) * 68 + kb + t    ]);
            a[2] = __float_as_uint(sQ[(rowA    ) * 68 + kb + t + 4]);
            a[3] = __float_as_uint(sQ[(rowA + 8) * 68 + kb + t + 4]);
            #pragma unroll
            for (int nj = 0; nj < 8; nj++) {
                uint32_t b0 = __float_as_uint(sK[(g + 8 * nj) * 68 + kb + t    ]);
                uint32_t b1 = __float_as_uint(sK[(g + 8 * nj) * 68 + kb + t + 4]);
                mma_tf32(cs[nj], a, b0, b1);
            }
        }

        float mx0 = -1e30f, mx1 = -1e30f;
        #pragma unroll
        for (int nj = 0; nj < 8; nj++) {
            const int c0m = sMk[8 * nj + 2 * t];
            const int c1m = sMk[8 * nj + 2 * t + 1];
            cs[nj][0] = c0m ? cs[nj][0] * 0.125f : -1e9f;
            cs[nj][1] = c1m ? cs[nj][1] * 0.125f : -1e9f;
            cs[nj][2] = c0m ? cs[nj][2] * 0.125f : -1e9f;
            cs[nj][3] = c1m ? cs[nj][3] * 0.125f : -1e9f;
            mx0 = fmaxf(mx0, fmaxf(cs[nj][0], cs[nj][1]));
            mx1 = fmaxf(mx1, fmaxf(cs[nj][2], cs[nj][3]));
        }
        #pragma unroll
        for (int d = 1; d < 4; d <<= 1) {
            mx0 = fmaxf(mx0, __shfl_xor_sync(FULL, mx0, d));
            mx1 = fmaxf(mx1, __shfl_xor_sync(FULL, mx1, d));
        }
        const float mn0 = fmaxf(m0r, mx0);
        const float mn1 = fmaxf(m1r, mx1);
        const float cr0 = __expf(m0r - mn0);
        const float cr1 = __expf(m1r - mn1);
        #pragma unroll
        for (int nj = 0; nj < 8; nj++) {
            co[nj][0] *= cr0; co[nj][1] *= cr0;
            co[nj][2] *= cr1; co[nj][3] *= cr1;
        }
        float ps0 = 0.0f, ps1 = 0.0f;
        #pragma unroll
        for (int nj = 0; nj < 8; nj++) {
            cs[nj][0] = __expf(cs[nj][0] - mn0);
            cs[nj][1] = __expf(cs[nj][1] - mn0);
            cs[nj][2] = __expf(cs[nj][2] - mn1);
            cs[nj][3] = __expf(cs[nj][3] - mn1);
            ps0 += cs[nj][0] + cs[nj][1];
            ps1 += cs[nj][2] + cs[nj][3];
        }
        #pragma unroll
        for (int d = 1; d < 4; d <<= 1) {
            ps0 += __shfl_xor_sync(FULL, ps0, d);
            ps1 += __shfl_xor_sync(FULL, ps1, d);
        }
        l0 = l0 * cr0 + ps0;
        l1 = l1 * cr1 + ps1;
        m0r = mn0; m1r = mn1;

        #pragma unroll
        for (int ks = 0; ks < 8; ks++) {
            float x0 = __shfl_sync(FULL, cs[ks][0], s0l);
            float x1 = __shfl_sync(FULL, cs[ks][1], s0l);
            float x2 = __shfl_sync(FULL, cs[ks][2], s0l);
            float x3 = __shfl_sync(FULL, cs[ks][3], s0l);
            float y0 = __shfl_sync(FULL, cs[ks][0], s1l);
            float y1 = __shfl_sync(FULL, cs[ks][1], s1l);
            float y2 = __shfl_sync(FULL, cs[ks][2], s1l);
            float y3 = __shfl_sync(FULL, cs[ks][3], s1l);
            uint32_t a[4];
            a[0] = to_tf32(todd ? x1 : x0);
            a[1] = to_tf32(todd ? x3 : x2);
            a[2] = to_tf32(todd ? y1 : y0);
            a[3] = to_tf32(todd ? y3 : y2);
            const int kb = ks * 8;
            #pragma unroll
            for (int nj = 0; nj < 8; nj++) {
                uint32_t b0 = __float_as_uint(sV[(kb + t    ) * 72 + 8 * nj + g]);
                uint32_t b1 = __float_as_uint(sV[(kb + t + 4) * 72 + 8 * nj + g]);
                mma_tf32(co[nj], a, b0, b1);
            }
        }

        if (kt + 1 < S_ / 64) {
            CP_WAIT(0);
            __syncthreads();
            round_kv(cur ^ 1);
            __syncthreads();
        }
    }

    const float inv0 = 1.0f / l0;
    const float inv1 = 1.0f / l1;
    #pragma unroll
    for (int nj = 0; nj < 8; nj++) {
        const int d = 8 * nj + 2 * t;
        float2 v0 = make_float2(co[nj][0] * inv0, co[nj][1] * inv0);
        float2 v1 = make_float2(co[nj][2] * inv1, co[nj][3] * inv1);
        *(float2*)(gx + ((size_t)b * S_ + q0 + rowA    ) * D_ + h * DK_ + d) = v0;
        *(float2*)(gx + ((size_t)b * S_ + q0 + rowA + 8) * D_ + h * DK_ + d) = v1;
    }
}

extern "C" void kernel_launch(void* const* d_in, const int* in_sizes, int n_in,
                              void* d_out, int out_size)
{
    const float* query = (const float*)d_in[0];
    const float* key_  = (const float*)d_in[1];
    const float* value = (const float*)d_in[2];
    const int*   mask  = (const int*)d_in[3];
    const float* Wq = (const float*)d_in[4];
    const float* bq = (const float*)d_in[5];
    const float* Wk = (const float*)d_in[6];
    const float* bk = (const float*)d_in[7];
    const float* Wv = (const float*)d_in[8];
    const float* bv = (const float*)d_in[9];
    const float* Wo = (const float*)d_in[10];
    const float* bo = (const float*)d_in[11];
    float* out = (float*)d_out;

    float *gq, *gk, *gv, *gx;
    cudaGetSymbolAddress((void**)&gq, g_q);
    cudaGetSymbolAddress((void**)&gk, g_k);
    cudaGetSymbolAddress((void**)&gv, g_v);
    cudaGetSymbolAddress((void**)&gx, g_x);

    cudaFuncSetAttribute(gemm_qkv, cudaFuncAttributeMaxDynamicSharedMemorySize, GK_SMEM);
    cudaFuncSetAttribute(gemm_out, cudaFuncAttributeMaxDynamicSharedMemorySize, GK_SMEM);
    cudaFuncSetAttribute(attn_mma, cudaFuncAttributeMaxDynamicSharedMemorySize, ATTN_SMEM_BYTES);

    // Prologue: split weights into bf16 hi/lo planes (one shot, ~5 us)
    dim3 gSplit(WPLANE / 256, 1, 4);            // (1152, 1, 4)
    split_w_kernel<<<gSplit, 256>>>(Wq, Wk, Wv, Wo);

    dim3 gProj(D_ / 128, (B_ * S_) / 128, 3);   // (6, 64, 3)
    gemm_qkv<<<gProj, 256, GK_SMEM>>>(query, key_, value, bq, bk, bv, gq, gk, gv);

    dim3 gAttn(S_ / 128, H_, B_);               // (16, 12, 4)
    attn_mma<<<gAttn, 256, ATTN_SMEM_BYTES>>>(gq, gk, gv, mask, gx);

    dim3 gOut(D_ / 128, (B_ * S_) / 128);       // (6, 64)
    gemm_out<<<gOut, 256, GK_SMEM>>>(gx, bo, out);
}